// round 3
// baseline (speedup 1.0000x reference)
#include <cuda_runtime.h>

#define NN   50000
#define EE   800000
#define HIDC 256
#define OUTC 128

// ---------------- scratch (static device globals; no allocation) ----------------
__device__ int   d_is64;
__device__ int   d_deg[NN];
__device__ float d_dinv[NN];
__device__ int   d_rowptr[NN + 1];
__device__ int   d_cursor[NN];
__device__ int   d_csr_src[EE];
__device__ float d_csr_w[EE];
__device__ float d_h0[(size_t)NN * HIDC];   // x @ W1
__device__ float d_h [(size_t)NN * HIDC];   // relu(Agg(h0) + b1)
__device__ float d_g [(size_t)NN * HIDC];   // Agg(h)
__device__ float d_Bcat[HIDC * 256];        // [W_mu | W_ls]
__device__ float d_bcat[256];               // [b_mu | b_ls]

// ---------------- edge-index dtype detection ----------------
// Indices are uniform in [0, 50000). If buffer is int64, every u64 word < 2^32.
// If buffer is int32, u64 word i = idx[2i] + idx[2i+1]*2^32 >= 2^32 unless
// idx[2i+1]==0 (p=1/50000). 128 words -> misclassification prob ~0.
__global__ void k_detect(const unsigned long long* __restrict__ ei) {
    if (threadIdx.x == 0 && blockIdx.x == 0) {
        int is64 = 1;
        for (int i = 0; i < 128; i++)
            if (ei[i] >= (1ull << 32)) { is64 = 0; break; }
        d_is64 = is64;
    }
}

__device__ __forceinline__ int load_idx(const void* ei, size_t pos) {
    if (d_is64) return (int)((const long long*)ei)[pos];
    return ((const int*)ei)[pos];
}

// ---------------- setup kernels ----------------
__global__ void k_init_deg() {
    int i = blockIdx.x * 256 + threadIdx.x;
    if (i < NN) d_deg[i] = 1;   // self loop
}

__global__ void k_count(const void* __restrict__ ei) {
    int e = blockIdx.x * 256 + threadIdx.x;
    if (e < EE) {
        int dst = load_idx(ei, (size_t)EE + e);
        atomicAdd(&d_deg[dst], 1);
    }
}

__global__ void k_dinv() {
    int i = blockIdx.x * 256 + threadIdx.x;
    if (i < NN) d_dinv[i] = rsqrtf((float)d_deg[i]);
}

// single-block scan over (deg-1) -> rowptr / cursor
__global__ void k_scan() {
    __shared__ int sw[32];
    int tid = threadIdx.x, lane = tid & 31, wid = tid >> 5;
    int offset = 0;
    if (tid == 0) d_rowptr[0] = 0;
    for (int base = 0; base < NN; base += 1024) {
        int i = base + tid;
        int v = (i < NN) ? (d_deg[i] - 1) : 0;
        int x = v;
#pragma unroll
        for (int d = 1; d < 32; d <<= 1) {
            int t = __shfl_up_sync(0xffffffffu, x, d);
            if (lane >= d) x += t;
        }
        if (lane == 31) sw[wid] = x;
        __syncthreads();
        if (wid == 0) {
            int y = sw[lane];
#pragma unroll
            for (int d = 1; d < 32; d <<= 1) {
                int t = __shfl_up_sync(0xffffffffu, y, d);
                if (lane >= d) y += t;
            }
            sw[lane] = y;
        }
        __syncthreads();
        int excl_w = (wid > 0) ? sw[wid - 1] : 0;
        int incl = x + excl_w + offset;
        if (i < NN) {
            d_rowptr[i + 1] = incl;
            d_cursor[i]     = incl - v;  // exclusive prefix = rowptr[i]
        }
        offset += sw[31];
        __syncthreads();
    }
}

__global__ void k_fill(const void* __restrict__ ei) {
    int e = blockIdx.x * 256 + threadIdx.x;
    if (e < EE) {
        int s = load_idx(ei, (size_t)e);
        int d = load_idx(ei, (size_t)EE + e);
        int pos = atomicAdd(&d_cursor[d], 1);
        d_csr_src[pos] = s;
        d_csr_w[pos]   = d_dinv[s] * d_dinv[d];
    }
}

__global__ void k_pack(const float* __restrict__ Wmu, const float* __restrict__ Wls,
                       const float* __restrict__ bmu, const float* __restrict__ bls) {
    int idx = blockIdx.x * 256 + threadIdx.x;
    if (idx < HIDC * 256) {
        int k = idx >> 8, j = idx & 255;
        d_Bcat[idx] = (j < OUTC) ? Wmu[k * OUTC + j] : Wls[k * OUTC + (j - OUTC)];
    }
    if (idx < 256) d_bcat[idx] = (idx < OUTC) ? bmu[idx] : bls[idx - OUTC];
}

// ---------------- aggregation (gather via CSR, no float atomics) ----------------
// BUF=0: d_h0 -> d_h with relu+bias.  BUF=1: d_h -> d_g plain.
// block: (64, 4) -> 4 nodes/block, 64 lanes x float4 cover 256 features
template <int BUF>
__global__ __launch_bounds__(256) void k_agg(const float* __restrict__ bias) {
    int node = blockIdx.x * 4 + threadIdx.y;
    if (node >= NN) return;
    int f4 = threadIdx.x;  // 0..63
    const float4* sf = (BUF == 0) ? (const float4*)d_h0 : (const float4*)d_h;
    float4*       df = (BUF == 0) ? (float4*)d_h        : (float4*)d_g;

    float di = d_dinv[node];
    float w0 = di * di;
    float4 acc = sf[(size_t)node * 64 + f4];
    acc.x *= w0; acc.y *= w0; acc.z *= w0; acc.w *= w0;

    int beg = d_rowptr[node], end = d_rowptr[node + 1];
    for (int e = beg; e < end; e++) {
        int   s = d_csr_src[e];
        float w = d_csr_w[e];
        float4 v = sf[(size_t)s * 64 + f4];
        acc.x += w * v.x;
        acc.y += w * v.y;
        acc.z += w * v.z;
        acc.w += w * v.w;
    }
    if (BUF == 0) {
        float4 b = ((const float4*)bias)[f4];
        acc.x = fmaxf(acc.x + b.x, 0.f);
        acc.y = fmaxf(acc.y + b.y, 0.f);
        acc.z = fmaxf(acc.z + b.z, 0.f);
        acc.w = fmaxf(acc.w + b.w, 0.f);
    }
    df[(size_t)node * 64 + f4] = acc;
}

// ---------------- fp32 GEMM core: 128x128 tile, BK=8, 256 thr, 8x8/thread -------
// MODE 0: C = A(param) @ B(param) -> d_h0, ld 256.
// MODE 1: C = d_g @ d_Bcat + d_bcat, split-store mu/ls into param Cp.
template <int MODE>
__global__ __launch_bounds__(256) void k_gemm(const float* __restrict__ Ap,
                                              const float* __restrict__ Bp,
                                              float* __restrict__ Cp, int M) {
    const int K = 256, NC = 256;
    __shared__ float As[8][132];   // padded to dodge STS bank conflicts
    __shared__ float Bs[8][128];

    const float* A = (MODE == 0) ? Ap : d_g;
    const float* B = (MODE == 0) ? Bp : d_Bcat;

    int tid = threadIdx.x;
    int bm = blockIdx.y * 128;
    int bn = blockIdx.x * 128;
    int tx = tid & 15;   // col group
    int ty = tid >> 4;   // row group

    float acc[8][8];
#pragma unroll
    for (int i = 0; i < 8; i++)
#pragma unroll
        for (int j = 0; j < 8; j++) acc[i][j] = 0.f;

    int arow = tid >> 1;
    int acol = (tid & 1) * 4;
    int brow = tid >> 5;
    int bcol = (tid & 31) * 4;

    bool avalid = (bm + arow) < M;
    const float* Aptr = A + (size_t)(bm + arow) * K + acol;
    const float* Bptr = B + (size_t)brow * NC + bn + bcol;

    for (int k0 = 0; k0 < K; k0 += 8) {
        float4 a4 = avalid ? *(const float4*)(Aptr + k0) : make_float4(0.f, 0.f, 0.f, 0.f);
        float4 b4 = *(const float4*)(Bptr + (size_t)k0 * NC);
        As[acol + 0][arow] = a4.x;
        As[acol + 1][arow] = a4.y;
        As[acol + 2][arow] = a4.z;
        As[acol + 3][arow] = a4.w;
        *(float4*)&Bs[brow][bcol] = b4;
        __syncthreads();

#pragma unroll
        for (int kk = 0; kk < 8; kk++) {
            float ar[8], br[8];
            *(float4*)(ar)     = *(const float4*)&As[kk][ty * 8];
            *(float4*)(ar + 4) = *(const float4*)&As[kk][ty * 8 + 4];
            *(float4*)(br)     = *(const float4*)&Bs[kk][tx * 8];
            *(float4*)(br + 4) = *(const float4*)&Bs[kk][tx * 8 + 4];
#pragma unroll
            for (int i = 0; i < 8; i++)
#pragma unroll
                for (int j = 0; j < 8; j++) acc[i][j] += ar[i] * br[j];
        }
        __syncthreads();
    }

#pragma unroll
    for (int i = 0; i < 8; i++) {
        int row = bm + ty * 8 + i;
        if (row >= M) break;
        int col0 = bn + tx * 8;
        if (MODE == 0) {
#pragma unroll
            for (int j = 0; j < 8; j += 4) {
                float4 v = make_float4(acc[i][j], acc[i][j + 1], acc[i][j + 2], acc[i][j + 3]);
                *(float4*)&d_h0[(size_t)row * NC + col0 + j] = v;
            }
        } else {
            float* base = (col0 < OUTC)
                              ? (Cp + (size_t)row * OUTC + col0)
                              : (Cp + (size_t)M * OUTC + (size_t)row * OUTC + (col0 - OUTC));
#pragma unroll
            for (int j = 0; j < 8; j += 4) {
                float4 v;
                v.x = acc[i][j]     + d_bcat[col0 + j];
                v.y = acc[i][j + 1] + d_bcat[col0 + j + 1];
                v.z = acc[i][j + 2] + d_bcat[col0 + j + 2];
                v.w = acc[i][j + 3] + d_bcat[col0 + j + 3];
                *(float4*)(base + j) = v;
            }
        }
    }
}

// ---------------- launch ----------------
extern "C" void kernel_launch(void* const* d_in, const int* in_sizes, int n_in,
                              void* d_out, int out_size) {
    const float* x   = (const float*)d_in[0];
    const void*  ei  = d_in[1];
    const float* W1  = (const float*)d_in[2];
    const float* b1  = (const float*)d_in[3];
    const float* Wmu = (const float*)d_in[4];
    const float* bmu = (const float*)d_in[5];
    const float* Wls = (const float*)d_in[6];
    const float* bls = (const float*)d_in[7];
    float* out = (float*)d_out;

    k_detect<<<1, 32>>>((const unsigned long long*)ei);
    k_init_deg<<<(NN + 255) / 256, 256>>>();
    k_count<<<(EE + 255) / 256, 256>>>(ei);
    k_dinv<<<(NN + 255) / 256, 256>>>();
    k_scan<<<1, 1024>>>();
    k_fill<<<(EE + 255) / 256, 256>>>(ei);
    k_pack<<<(HIDC * 256 + 255) / 256, 256>>>(Wmu, Wls, bmu, bls);

    dim3 gemm_grid(2, (NN + 127) / 128);
    k_gemm<0><<<gemm_grid, 256>>>(x, W1, nullptr, NN);

    dim3 agg_grid((NN + 3) / 4);
    dim3 agg_blk(64, 4);
    k_agg<0><<<agg_grid, agg_blk>>>(b1);
    k_agg<1><<<agg_grid, agg_blk>>>(nullptr);

    k_gemm<1><<<gemm_grid, 256>>>(nullptr, nullptr, out, NN);
}

// round 7
// speedup vs baseline: 1.3091x; 1.3091x over previous
#include <cuda_runtime.h>
#include <cuda_bf16.h>
#include <cstdint>

#define NN   50000
#define EE   800000
#define HIDC 256
#define OUTC 128

// ---------------- scratch (static device globals; no allocation) ----------------
__device__ int   d_is64;
__device__ int   d_deg[NN];
__device__ float d_dinv[NN];
__device__ int   d_rowptr[NN + 1];
__device__ int   d_cursor[NN];
__device__ int   d_csr_src[EE];
__device__ float d_csr_w[EE];
__device__ float d_h0[(size_t)NN * HIDC];      // x @ W1
__device__ float d_h [(size_t)NN * HIDC];      // relu(Agg(h0) + b1)
__device__ __nv_bfloat16 d_xhi[(size_t)NN * HIDC];
__device__ __nv_bfloat16 d_xlo[(size_t)NN * HIDC];
__device__ __nv_bfloat16 d_ghi[(size_t)NN * HIDC];  // split of Agg(h)
__device__ __nv_bfloat16 d_glo[(size_t)NN * HIDC];
__device__ __nv_bfloat16 d_W1Thi[HIDC * HIDC];  // W1^T  [n][k]
__device__ __nv_bfloat16 d_W1Tlo[HIDC * HIDC];
__device__ __nv_bfloat16 d_BcThi[HIDC * HIDC];  // [Wmu|Wls]^T  [n][k]
__device__ __nv_bfloat16 d_BcTlo[HIDC * HIDC];
__device__ float d_bcat[256];                   // [b_mu | b_ls]

// ---------------- helpers ----------------
__device__ __forceinline__ uint32_t smem_u32(const void* p) {
    uint32_t a;
    asm("{ .reg .u64 t; cvta.to.shared.u64 t, %1; cvt.u32.u64 %0, t; }" : "=r"(a) : "l"(p));
    return a;
}
__device__ __forceinline__ void bsplit(float v, __nv_bfloat16& h, __nv_bfloat16& l) {
    h = __float2bfloat16(v);
    l = __float2bfloat16(v - __bfloat162float(h));
}
__device__ __forceinline__ void ldmat_x4(uint32_t& r0, uint32_t& r1, uint32_t& r2,
                                         uint32_t& r3, uint32_t addr) {
    asm volatile("ldmatrix.sync.aligned.m8n8.x4.shared.b16 {%0,%1,%2,%3}, [%4];"
                 : "=r"(r0), "=r"(r1), "=r"(r2), "=r"(r3) : "r"(addr));
}
__device__ __forceinline__ void mma_bf16(float* c, const uint32_t* a,
                                         uint32_t b0, uint32_t b1) {
    asm volatile("mma.sync.aligned.m16n8k16.row.col.f32.bf16.bf16.f32 "
                 "{%0,%1,%2,%3}, {%4,%5,%6,%7}, {%8,%9}, {%0,%1,%2,%3};"
                 : "+f"(c[0]), "+f"(c[1]), "+f"(c[2]), "+f"(c[3])
                 : "r"(a[0]), "r"(a[1]), "r"(a[2]), "r"(a[3]), "r"(b0), "r"(b1));
}
// swizzled smem addr: 128B rows, 16B chunk c -> c ^ (row&7)
__device__ __forceinline__ uint32_t sw_addr(uint32_t base, int row, int kc) {
    return base + row * 128 + ((kc ^ (row & 7)) << 4);
}

// ---------------- edge-index dtype detection ----------------
__global__ void k_detect(const unsigned long long* __restrict__ ei) {
    if (threadIdx.x == 0 && blockIdx.x == 0) {
        int is64 = 1;
        for (int i = 0; i < 128; i++)
            if (ei[i] >= (1ull << 32)) { is64 = 0; break; }
        d_is64 = is64;
    }
}
__device__ __forceinline__ int load_idx(const void* ei, size_t pos) {
    if (d_is64) return (int)((const long long*)ei)[pos];
    return ((const int*)ei)[pos];
}

// ---------------- setup kernels ----------------
__global__ void k_init_deg() {
    int i = blockIdx.x * 256 + threadIdx.x;
    if (i < NN) d_deg[i] = 1;
}
__global__ void k_count(const void* __restrict__ ei) {
    int e = blockIdx.x * 256 + threadIdx.x;
    if (e < EE) atomicAdd(&d_deg[load_idx(ei, (size_t)EE + e)], 1);
}
__global__ void k_dinv() {
    int i = blockIdx.x * 256 + threadIdx.x;
    if (i < NN) d_dinv[i] = rsqrtf((float)d_deg[i]);
}
__global__ void k_scan() {
    __shared__ int sw[32];
    int tid = threadIdx.x, lane = tid & 31, wid = tid >> 5;
    int offset = 0;
    if (tid == 0) d_rowptr[0] = 0;
    for (int base = 0; base < NN; base += 1024) {
        int i = base + tid;
        int v = (i < NN) ? (d_deg[i] - 1) : 0;
        int x = v;
#pragma unroll
        for (int d = 1; d < 32; d <<= 1) {
            int t = __shfl_up_sync(0xffffffffu, x, d);
            if (lane >= d) x += t;
        }
        if (lane == 31) sw[wid] = x;
        __syncthreads();
        if (wid == 0) {
            int y = sw[lane];
#pragma unroll
            for (int d = 1; d < 32; d <<= 1) {
                int t = __shfl_up_sync(0xffffffffu, y, d);
                if (lane >= d) y += t;
            }
            sw[lane] = y;
        }
        __syncthreads();
        int excl_w = (wid > 0) ? sw[wid - 1] : 0;
        int incl = x + excl_w + offset;
        if (i < NN) {
            d_rowptr[i + 1] = incl;
            d_cursor[i]     = incl - v;
        }
        offset += sw[31];
        __syncthreads();
    }
}
__global__ void k_fill(const void* __restrict__ ei) {
    int e = blockIdx.x * 256 + threadIdx.x;
    if (e < EE) {
        int s = load_idx(ei, (size_t)e);
        int d = load_idx(ei, (size_t)EE + e);
        int pos = atomicAdd(&d_cursor[d], 1);
        d_csr_src[pos] = s;
        d_csr_w[pos]   = d_dinv[s] * d_dinv[d];
    }
}

// pack + transpose + bf16-split the weights
__global__ void k_pack2(const float* __restrict__ W1,
                        const float* __restrict__ Wmu, const float* __restrict__ Wls,
                        const float* __restrict__ bmu, const float* __restrict__ bls) {
    int idx = blockIdx.x * 256 + threadIdx.x;
    if (idx < 65536) {
        int n = idx >> 8, k = idx & 255;
        bsplit(W1[k * 256 + n], d_W1Thi[idx], d_W1Tlo[idx]);
        float bc = (n < OUTC) ? Wmu[k * OUTC + n] : Wls[k * OUTC + (n - OUTC)];
        bsplit(bc, d_BcThi[idx], d_BcTlo[idx]);
    }
    if (idx < 256) d_bcat[idx] = (idx < OUTC) ? bmu[idx] : bls[idx - OUTC];
}

__global__ void k_splitx(const float* __restrict__ x) {
    int i = blockIdx.x * 256 + threadIdx.x;
    if (i < NN * HIDC) bsplit(x[i], d_xhi[i], d_xlo[i]);
}

// ---------------- aggregation (gather via CSR, no float atomics) ----------------
// BUF=0: d_h0 -> d_h (relu+bias). BUF=1: d_h -> (d_ghi, d_glo).
template <int BUF>
__global__ __launch_bounds__(256) void k_agg(const float* __restrict__ bias) {
    int node = blockIdx.x * 4 + threadIdx.y;
    if (node >= NN) return;
    int f4 = threadIdx.x;  // 0..63
    const float4* sf = (BUF == 0) ? (const float4*)d_h0 : (const float4*)d_h;

    float di = d_dinv[node];
    float w0 = di * di;
    float4 acc = sf[(size_t)node * 64 + f4];
    acc.x *= w0; acc.y *= w0; acc.z *= w0; acc.w *= w0;

    int beg = d_rowptr[node], end = d_rowptr[node + 1];
    for (int e = beg; e < end; e++) {
        int   s = d_csr_src[e];
        float w = d_csr_w[e];
        float4 v = sf[(size_t)s * 64 + f4];
        acc.x += w * v.x;
        acc.y += w * v.y;
        acc.z += w * v.z;
        acc.w += w * v.w;
    }
    if (BUF == 0) {
        float4 b = ((const float4*)bias)[f4];
        acc.x = fmaxf(acc.x + b.x, 0.f);
        acc.y = fmaxf(acc.y + b.y, 0.f);
        acc.z = fmaxf(acc.z + b.z, 0.f);
        acc.w = fmaxf(acc.w + b.w, 0.f);
        ((float4*)d_h)[(size_t)node * 64 + f4] = acc;
    } else {
        __nv_bfloat16 h0, l0, h1, l1, h2, l2, h3, l3;
        bsplit(acc.x, h0, l0); bsplit(acc.y, h1, l1);
        bsplit(acc.z, h2, l2); bsplit(acc.w, h3, l3);
        uint2 hv, lv;
        hv.x = (uint32_t)__bfloat16_as_ushort(h0) | ((uint32_t)__bfloat16_as_ushort(h1) << 16);
        hv.y = (uint32_t)__bfloat16_as_ushort(h2) | ((uint32_t)__bfloat16_as_ushort(h3) << 16);
        lv.x = (uint32_t)__bfloat16_as_ushort(l0) | ((uint32_t)__bfloat16_as_ushort(l1) << 16);
        lv.y = (uint32_t)__bfloat16_as_ushort(l2) | ((uint32_t)__bfloat16_as_ushort(l3) << 16);
        *(uint2*)&d_ghi[(size_t)node * 256 + f4 * 4] = hv;
        *(uint2*)&d_glo[(size_t)node * 256 + f4 * 4] = lv;
    }
}

// ---------------- mma.sync bf16-split GEMM ----------------
// C[M x 256] = A[M x 256] @ B^T  (B stored N-major [256n][256k])
// 128x128 CTA tile, K in 4 chunks of 64, 8 warps (4m x 2n), warp tile 32x64.
// 3-term Markidis: acc += Ahi*Bhi + Ahi*Blo + Alo*Bhi (fp32 acc in regs).
#define TILE_B 16384          // 128 rows x 128 bytes (64 bf16), swizzled
#define GSMEM  (4 * TILE_B)

// load 128 rows x 64 bf16 chunk into swizzled smem tile (256 threads)
__device__ __forceinline__ void load_tile64(char* tile, const __nv_bfloat16* __restrict__ src,
                                            int row0, int nvalid, int col0) {
    int t = threadIdx.x;
    int r = t >> 1;
    int hb = (t & 1) * 64;
    const char* srow = (const char*)(src + (size_t)(row0 + r) * 256 + col0);
    bool valid = r < nvalid;
#pragma unroll
    for (int i = 0; i < 4; i++) {
        int b = hb + i * 16;
        uint4 v = valid ? *(const uint4*)(srow + b) : make_uint4(0u, 0u, 0u, 0u);
        uint32_t off = (uint32_t)(r * 128 + b);
        off ^= ((off >> 3) & 0x70);
        *(uint4*)(tile + off) = v;
    }
}

template <int MODE>
__global__ __launch_bounds__(256) void k_gemm_mma(float* __restrict__ Cp) {
    extern __shared__ char smem[];
    char* sAhi = smem;
    char* sAlo = smem + TILE_B;
    char* sBhi = smem + 2 * TILE_B;
    char* sBlo = smem + 3 * TILE_B;
    uint32_t bAhi = smem_u32(sAhi), bAlo = bAhi + TILE_B;
    uint32_t bBhi = bAhi + 2 * TILE_B, bBlo = bAhi + 3 * TILE_B;

    int tid = threadIdx.x, wid = tid >> 5, lane = tid & 31;
    int wm = wid >> 1, wn = wid & 1;
    int bn = blockIdx.x * 128;
    int bm = blockIdx.y * 128;

    const __nv_bfloat16* Ahi = (MODE == 0) ? d_xhi : d_ghi;
    const __nv_bfloat16* Alo = (MODE == 0) ? d_xlo : d_glo;
    const __nv_bfloat16* Bhi = (MODE == 0) ? d_W1Thi : d_BcThi;
    const __nv_bfloat16* Blo = (MODE == 0) ? d_W1Tlo : d_BcTlo;

    int navalid = NN - bm; if (navalid > 128) navalid = 128;

    float acc[2][8][4];
#pragma unroll
    for (int i = 0; i < 2; i++)
#pragma unroll
        for (int j = 0; j < 8; j++)
#pragma unroll
            for (int q = 0; q < 4; q++) acc[i][j][q] = 0.f;

    // ldmatrix addressing (lane-dependent, chunk-invariant parts)
    int a_row_off = ((lane >> 3) & 1) * 8 + (lane & 7);   // within m16 tile
    int a_kc_off  = (lane >> 4);                          // 0/1 -> k halves
    int b_row_off = (lane >> 4) * 8 + (lane & 7);         // within n16 group
    int b_kc_off  = ((lane >> 3) & 1);

    for (int c = 0; c < 4; c++) {
        if (c > 0) __syncthreads();
        load_tile64(sAhi, Ahi, bm, navalid, c * 64);
        load_tile64(sAlo, Alo, bm, navalid, c * 64);
        load_tile64(sBhi, Bhi, bn, 128, c * 64);
        load_tile64(sBlo, Blo, bn, 128, c * 64);
        __syncthreads();

#pragma unroll
        for (int ks = 0; ks < 4; ks++) {
            int kc0 = ks * 2;
            uint32_t ahi[2][4], alo[2][4];
#pragma unroll
            for (int mi = 0; mi < 2; mi++) {
                int row = wm * 32 + mi * 16 + a_row_off;
                int kc  = kc0 + a_kc_off;
                ldmat_x4(ahi[mi][0], ahi[mi][1], ahi[mi][2], ahi[mi][3],
                         sw_addr(bAhi, row, kc));
                ldmat_x4(alo[mi][0], alo[mi][1], alo[mi][2], alo[mi][3],
                         sw_addr(bAlo, row, kc));
            }
#pragma unroll
            for (int ng = 0; ng < 4; ng++) {
                int nrow = wn * 64 + ng * 16 + b_row_off;
                int kc   = kc0 + b_kc_off;
                uint32_t bh[4], bl[4];
                ldmat_x4(bh[0], bh[1], bh[2], bh[3], sw_addr(bBhi, nrow, kc));
                ldmat_x4(bl[0], bl[1], bl[2], bl[3], sw_addr(bBlo, nrow, kc));
#pragma unroll
                for (int mi = 0; mi < 2; mi++) {
                    mma_bf16(acc[mi][ng * 2],     ahi[mi], bh[0], bh[1]);
                    mma_bf16(acc[mi][ng * 2],     ahi[mi], bl[0], bl[1]);
                    mma_bf16(acc[mi][ng * 2],     alo[mi], bh[0], bh[1]);
                    mma_bf16(acc[mi][ng * 2 + 1], ahi[mi], bh[2], bh[3]);
                    mma_bf16(acc[mi][ng * 2 + 1], ahi[mi], bl[2], bl[3]);
                    mma_bf16(acc[mi][ng * 2 + 1], alo[mi], bh[2], bh[3]);
                }
            }
        }
    }

    // epilogue: c frag layout: lane -> rows (l>>2), (l>>2)+8; cols (l&3)*2, +1
#pragma unroll
    for (int mi = 0; mi < 2; mi++) {
        int r0 = bm + wm * 32 + mi * 16 + (lane >> 2);
#pragma unroll
        for (int ni = 0; ni < 8; ni++) {
            int col = wn * 64 + ni * 8 + (lane & 3) * 2;  // 0..127 within CTA n-tile
            float* a = acc[mi][ni];
            if (MODE == 0) {
                if (r0 < NN)
                    *(float2*)&d_h0[(size_t)r0 * 256 + bn + col] = make_float2(a[0], a[1]);
                if (r0 + 8 < NN)
                    *(float2*)&d_h0[(size_t)(r0 + 8) * 256 + bn + col] = make_float2(a[2], a[3]);
            } else {
                float bx = d_bcat[bn + col], by = d_bcat[bn + col + 1];
                size_t half = (bn == 0) ? 0 : (size_t)NN * OUTC;
                if (r0 < NN)
                    *(float2*)&Cp[half + (size_t)r0 * OUTC + col] =
                        make_float2(a[0] + bx, a[1] + by);
                if (r0 + 8 < NN)
                    *(float2*)&Cp[half + (size_t)(r0 + 8) * OUTC + col] =
                        make_float2(a[2] + bx, a[3] + by);
            }
        }
    }
}

// ---------------- launch ----------------
extern "C" void kernel_launch(void* const* d_in, const int* in_sizes, int n_in,
                              void* d_out, int out_size) {
    const float* x   = (const float*)d_in[0];
    const void*  ei  = d_in[1];
    const float* W1  = (const float*)d_in[2];
    const float* b1  = (const float*)d_in[3];
    const float* Wmu = (const float*)d_in[4];
    const float* bmu = (const float*)d_in[5];
    const float* Wls = (const float*)d_in[6];
    const float* bls = (const float*)d_in[7];
    float* out = (float*)d_out;

    cudaFuncSetAttribute(k_gemm_mma<0>, cudaFuncAttributeMaxDynamicSharedMemorySize, GSMEM);
    cudaFuncSetAttribute(k_gemm_mma<1>, cudaFuncAttributeMaxDynamicSharedMemorySize, GSMEM);

    k_detect<<<1, 32>>>((const unsigned long long*)ei);
    k_pack2<<<(65536 + 255) / 256, 256>>>(W1, Wmu, Wls, bmu, bls);
    k_splitx<<<(NN * HIDC + 255) / 256, 256>>>(x);
    k_init_deg<<<(NN + 255) / 256, 256>>>();
    k_count<<<(EE + 255) / 256, 256>>>(ei);
    k_dinv<<<(NN + 255) / 256, 256>>>();
    k_scan<<<1, 1024>>>();
    k_fill<<<(EE + 255) / 256, 256>>>(ei);

    dim3 ggrid(2, (NN + 127) / 128);
    k_gemm_mma<0><<<ggrid, 256, GSMEM>>>(nullptr);

    dim3 agrid((NN + 3) / 4);
    dim3 ablk(64, 4);
    k_agg<0><<<agrid, ablk>>>(b1);
    k_agg<1><<<agrid, ablk>>>(nullptr);

    k_gemm_mma<1><<<ggrid, 256, GSMEM>>>(out);
}

// round 8
// speedup vs baseline: 1.3364x; 1.0208x over previous
#include <cuda_runtime.h>
#include <cuda_bf16.h>
#include <cstdint>

#define NN   50000
#define EE   800000
#define HIDC 256
#define OUTC 128

// ---------------- scratch (static device globals; no allocation) ----------------
__device__ int   d_is64;
__device__ int   d_deg[NN];
__device__ float d_dinv[NN];
__device__ int   d_rowptr[NN + 1];
__device__ int   d_cursor[NN];
__device__ int2  d_csr[EE];                    // (src, w as float bits)
__device__ float d_h0[(size_t)NN * HIDC];      // x @ W1
__device__ float d_h [(size_t)NN * HIDC];      // relu(Agg(h0) + b1)
__device__ __nv_bfloat16 d_ghi[(size_t)NN * HIDC];  // split of Agg(h)
__device__ __nv_bfloat16 d_glo[(size_t)NN * HIDC];
__device__ __nv_bfloat16 d_W1Thi[HIDC * HIDC];  // W1^T  [n][k]
__device__ __nv_bfloat16 d_W1Tlo[HIDC * HIDC];
__device__ __nv_bfloat16 d_BcThi[HIDC * HIDC];  // [Wmu|Wls]^T  [n][k]
__device__ __nv_bfloat16 d_BcTlo[HIDC * HIDC];
__device__ float d_bcat[256];                   // [b_mu | b_ls]

// ---------------- helpers ----------------
__device__ __forceinline__ uint32_t smem_u32(const void* p) {
    uint32_t a;
    asm("{ .reg .u64 t; cvta.to.shared.u64 t, %1; cvt.u32.u64 %0, t; }" : "=r"(a) : "l"(p));
    return a;
}
__device__ __forceinline__ void bsplit(float v, __nv_bfloat16& h, __nv_bfloat16& l) {
    h = __float2bfloat16(v);
    l = __float2bfloat16(v - __bfloat162float(h));
}
__device__ __forceinline__ void split2(float a, float b, uint32_t& h, uint32_t& l) {
    __nv_bfloat16 ha, la, hb, lb;
    bsplit(a, ha, la);
    bsplit(b, hb, lb);
    h = (uint32_t)__bfloat16_as_ushort(ha) | ((uint32_t)__bfloat16_as_ushort(hb) << 16);
    l = (uint32_t)__bfloat16_as_ushort(la) | ((uint32_t)__bfloat16_as_ushort(lb) << 16);
}
__device__ __forceinline__ void ldmat_x4(uint32_t& r0, uint32_t& r1, uint32_t& r2,
                                         uint32_t& r3, uint32_t addr) {
    asm volatile("ldmatrix.sync.aligned.m8n8.x4.shared.b16 {%0,%1,%2,%3}, [%4];"
                 : "=r"(r0), "=r"(r1), "=r"(r2), "=r"(r3) : "r"(addr));
}
__device__ __forceinline__ void mma_bf16(float* c, const uint32_t* a,
                                         uint32_t b0, uint32_t b1) {
    asm volatile("mma.sync.aligned.m16n8k16.row.col.f32.bf16.bf16.f32 "
                 "{%0,%1,%2,%3}, {%4,%5,%6,%7}, {%8,%9}, {%0,%1,%2,%3};"
                 : "+f"(c[0]), "+f"(c[1]), "+f"(c[2]), "+f"(c[3])
                 : "r"(a[0]), "r"(a[1]), "r"(a[2]), "r"(a[3]), "r"(b0), "r"(b1));
}
// swizzled smem addr: 128B rows, 16B chunk c -> c ^ (row&7)
__device__ __forceinline__ uint32_t sw_addr(uint32_t base, int row, int kc) {
    return base + row * 128 + ((kc ^ (row & 7)) << 4);
}
__device__ __forceinline__ int load_idx(const void* ei, size_t pos) {
    if (d_is64) return (int)((const long long*)ei)[pos];
    return ((const int*)ei)[pos];
}

// ---------------- setup kernels ----------------
// init deg to 1 (self loop) + detect edge dtype (block 0, thread 0)
__global__ void k_init(const unsigned long long* __restrict__ ei) {
    int i = blockIdx.x * 256 + threadIdx.x;
    if (i < NN) d_deg[i] = 1;
    if (i == 0) {
        int is64 = 1;
        for (int j = 0; j < 128; j++)
            if (ei[j] >= (1ull << 32)) { is64 = 0; break; }
        d_is64 = is64;
    }
}
__global__ void k_count(const void* __restrict__ ei) {
    int e = blockIdx.x * 256 + threadIdx.x;
    if (e < EE) atomicAdd(&d_deg[load_idx(ei, (size_t)EE + e)], 1);
}
// single-block scan over (deg-1) -> rowptr / cursor; also computes dinv
__global__ void k_scan() {
    __shared__ int sw[32];
    int tid = threadIdx.x, lane = tid & 31, wid = tid >> 5;
    int offset = 0;
    if (tid == 0) d_rowptr[0] = 0;
    for (int base = 0; base < NN; base += 1024) {
        int i = base + tid;
        int deg = (i < NN) ? d_deg[i] : 1;
        if (i < NN) d_dinv[i] = rsqrtf((float)deg);
        int v = deg - 1;
        int x = v;
#pragma unroll
        for (int d = 1; d < 32; d <<= 1) {
            int t = __shfl_up_sync(0xffffffffu, x, d);
            if (lane >= d) x += t;
        }
        if (lane == 31) sw[wid] = x;
        __syncthreads();
        if (wid == 0) {
            int y = sw[lane];
#pragma unroll
            for (int d = 1; d < 32; d <<= 1) {
                int t = __shfl_up_sync(0xffffffffu, y, d);
                if (lane >= d) y += t;
            }
            sw[lane] = y;
        }
        __syncthreads();
        int excl_w = (wid > 0) ? sw[wid - 1] : 0;
        int incl = x + excl_w + offset;
        if (i < NN) {
            d_rowptr[i + 1] = incl;
            d_cursor[i]     = incl - v;
        }
        offset += sw[31];
        __syncthreads();
    }
}
__global__ void k_fill(const void* __restrict__ ei) {
    int e = blockIdx.x * 256 + threadIdx.x;
    if (e < EE) {
        int s = load_idx(ei, (size_t)e);
        int d = load_idx(ei, (size_t)EE + e);
        int pos = atomicAdd(&d_cursor[d], 1);
        d_csr[pos] = make_int2(s, __float_as_int(d_dinv[s] * d_dinv[d]));
    }
}

// pack + transpose + bf16-split the weights
__global__ void k_pack2(const float* __restrict__ W1,
                        const float* __restrict__ Wmu, const float* __restrict__ Wls,
                        const float* __restrict__ bmu, const float* __restrict__ bls) {
    int idx = blockIdx.x * 256 + threadIdx.x;
    if (idx < 65536) {
        int n = idx >> 8, k = idx & 255;
        bsplit(W1[k * 256 + n], d_W1Thi[idx], d_W1Tlo[idx]);
        float bc = (n < OUTC) ? Wmu[k * OUTC + n] : Wls[k * OUTC + (n - OUTC)];
        bsplit(bc, d_BcThi[idx], d_BcTlo[idx]);
    }
    if (idx < 256) d_bcat[idx] = (idx < OUTC) ? bmu[idx] : bls[idx - OUTC];
}

// ---------------- aggregation (gather via CSR, no float atomics) ----------------
// BUF=0: d_h0 -> d_h (relu+bias). BUF=1: d_h -> (d_ghi, d_glo).
template <int BUF>
__global__ __launch_bounds__(256) void k_agg(const float* __restrict__ bias) {
    int node = blockIdx.x * 4 + threadIdx.y;
    if (node >= NN) return;
    int f4 = threadIdx.x;  // 0..63
    const float4* sf = (BUF == 0) ? (const float4*)d_h0 : (const float4*)d_h;

    float di = d_dinv[node];
    float w0 = di * di;
    float4 acc = sf[(size_t)node * 64 + f4];
    acc.x *= w0; acc.y *= w0; acc.z *= w0; acc.w *= w0;

    int beg = d_rowptr[node], end = d_rowptr[node + 1];
    int e = beg;
    for (; e + 4 <= end; e += 4) {
        int2 c0 = d_csr[e];
        int2 c1 = d_csr[e + 1];
        int2 c2 = d_csr[e + 2];
        int2 c3 = d_csr[e + 3];
        float4 v0 = sf[(size_t)c0.x * 64 + f4];
        float4 v1 = sf[(size_t)c1.x * 64 + f4];
        float4 v2 = sf[(size_t)c2.x * 64 + f4];
        float4 v3 = sf[(size_t)c3.x * 64 + f4];
        float w0f = __int_as_float(c0.y), w1f = __int_as_float(c1.y);
        float w2f = __int_as_float(c2.y), w3f = __int_as_float(c3.y);
        acc.x += w0f * v0.x + w1f * v1.x + w2f * v2.x + w3f * v3.x;
        acc.y += w0f * v0.y + w1f * v1.y + w2f * v2.y + w3f * v3.y;
        acc.z += w0f * v0.z + w1f * v1.z + w2f * v2.z + w3f * v3.z;
        acc.w += w0f * v0.w + w1f * v1.w + w2f * v2.w + w3f * v3.w;
    }
    for (; e < end; e++) {
        int2 c = d_csr[e];
        float w = __int_as_float(c.y);
        float4 v = sf[(size_t)c.x * 64 + f4];
        acc.x += w * v.x;
        acc.y += w * v.y;
        acc.z += w * v.z;
        acc.w += w * v.w;
    }
    if (BUF == 0) {
        float4 b = ((const float4*)bias)[f4];
        acc.x = fmaxf(acc.x + b.x, 0.f);
        acc.y = fmaxf(acc.y + b.y, 0.f);
        acc.z = fmaxf(acc.z + b.z, 0.f);
        acc.w = fmaxf(acc.w + b.w, 0.f);
        ((float4*)d_h)[(size_t)node * 64 + f4] = acc;
    } else {
        uint2 hv, lv;
        split2(acc.x, acc.y, hv.x, lv.x);
        split2(acc.z, acc.w, hv.y, lv.y);
        *(uint2*)&d_ghi[(size_t)node * 256 + f4 * 4] = hv;
        *(uint2*)&d_glo[(size_t)node * 256 + f4 * 4] = lv;
    }
}

// ---------------- mma.sync bf16-split GEMM ----------------
// C[M x 256] = A[M x 256] @ B^T  (B stored N-major [256n][256k])
// 128x128 CTA tile, K in 4 chunks of 64, 8 warps (4m x 2n), warp tile 32x64.
// 3-term Markidis: acc += Ahi*Bhi + Ahi*Blo + Alo*Bhi (fp32 acc in regs).
#define TILE_B 16384          // 128 rows x 128 bytes (64 bf16), swizzled
#define GSMEM  (4 * TILE_B)

// load 128 rows x 64 bf16 chunk into swizzled smem tile (256 threads)
__device__ __forceinline__ void load_tile64(char* tile, const __nv_bfloat16* __restrict__ src,
                                            int row0, int nvalid, int col0) {
    int t = threadIdx.x;
    int r = t >> 1;
    int hb = (t & 1) * 64;
    const char* srow = (const char*)(src + (size_t)(row0 + r) * 256 + col0);
    bool valid = r < nvalid;
#pragma unroll
    for (int i = 0; i < 4; i++) {
        int b = hb + i * 16;
        uint4 v = valid ? *(const uint4*)(srow + b) : make_uint4(0u, 0u, 0u, 0u);
        uint32_t off = (uint32_t)(r * 128 + b);
        off ^= ((off >> 3) & 0x70);
        *(uint4*)(tile + off) = v;
    }
}

// load 128 rows x 64 fp32 chunk, split into two swizzled bf16 tiles (256 threads)
__device__ __forceinline__ void load_tile64_split(char* tilehi, char* tilelo,
                                                  const float* __restrict__ src,
                                                  int row0, int nvalid, int col0) {
    int t = threadIdx.x;
    int r = t >> 1;
    int hf = (t & 1) * 32;  // 32 floats per thread
    const float* srow = src + (size_t)(row0 + r) * 256 + col0 + hf;
    bool valid = r < nvalid;
#pragma unroll
    for (int i = 0; i < 4; i++) {
        float4 f0 = valid ? *(const float4*)(srow + i * 8)     : make_float4(0.f, 0.f, 0.f, 0.f);
        float4 f1 = valid ? *(const float4*)(srow + i * 8 + 4) : make_float4(0.f, 0.f, 0.f, 0.f);
        uint4 hv, lv;
        split2(f0.x, f0.y, hv.x, lv.x);
        split2(f0.z, f0.w, hv.y, lv.y);
        split2(f1.x, f1.y, hv.z, lv.z);
        split2(f1.z, f1.w, hv.w, lv.w);
        uint32_t off = (uint32_t)(r * 128 + hf * 2 + i * 16);
        off ^= ((off >> 3) & 0x70);
        *(uint4*)(tilehi + off) = hv;
        *(uint4*)(tilelo + off) = lv;
    }
}

template <int MODE>
__global__ __launch_bounds__(256) void k_gemm_mma(const float* __restrict__ Ax,
                                                  float* __restrict__ Cp) {
    extern __shared__ char smem[];
    char* sAhi = smem;
    char* sAlo = smem + TILE_B;
    char* sBhi = smem + 2 * TILE_B;
    char* sBlo = smem + 3 * TILE_B;
    uint32_t bAhi = smem_u32(sAhi), bAlo = bAhi + TILE_B;
    uint32_t bBhi = bAhi + 2 * TILE_B, bBlo = bAhi + 3 * TILE_B;

    int tid = threadIdx.x, wid = tid >> 5, lane = tid & 31;
    int wm = wid >> 1, wn = wid & 1;
    int bn = blockIdx.x * 128;
    int bm = blockIdx.y * 128;

    const __nv_bfloat16* Bhi = (MODE == 0) ? d_W1Thi : d_BcThi;
    const __nv_bfloat16* Blo = (MODE == 0) ? d_W1Tlo : d_BcTlo;

    int navalid = NN - bm; if (navalid > 128) navalid = 128;

    float acc[2][8][4];
#pragma unroll
    for (int i = 0; i < 2; i++)
#pragma unroll
        for (int j = 0; j < 8; j++)
#pragma unroll
            for (int q = 0; q < 4; q++) acc[i][j][q] = 0.f;

    int a_row_off = ((lane >> 3) & 1) * 8 + (lane & 7);
    int a_kc_off  = (lane >> 4);
    int b_row_off = (lane >> 4) * 8 + (lane & 7);
    int b_kc_off  = ((lane >> 3) & 1);

    for (int c = 0; c < 4; c++) {
        if (c > 0) __syncthreads();
        if (MODE == 0) {
            load_tile64_split(sAhi, sAlo, Ax, bm, navalid, c * 64);
        } else {
            load_tile64(sAhi, d_ghi, bm, navalid, c * 64);
            load_tile64(sAlo, d_glo, bm, navalid, c * 64);
        }
        load_tile64(sBhi, Bhi, bn, 128, c * 64);
        load_tile64(sBlo, Blo, bn, 128, c * 64);
        __syncthreads();

#pragma unroll
        for (int ks = 0; ks < 4; ks++) {
            int kc0 = ks * 2;
            uint32_t ahi[2][4], alo[2][4];
#pragma unroll
            for (int mi = 0; mi < 2; mi++) {
                int row = wm * 32 + mi * 16 + a_row_off;
                int kc  = kc0 + a_kc_off;
                ldmat_x4(ahi[mi][0], ahi[mi][1], ahi[mi][2], ahi[mi][3],
                         sw_addr(bAhi, row, kc));
                ldmat_x4(alo[mi][0], alo[mi][1], alo[mi][2], alo[mi][3],
                         sw_addr(bAlo, row, kc));
            }
#pragma unroll
            for (int ng = 0; ng < 4; ng++) {
                int nrow = wn * 64 + ng * 16 + b_row_off;
                int kc   = kc0 + b_kc_off;
                uint32_t bh[4], bl[4];
                ldmat_x4(bh[0], bh[1], bh[2], bh[3], sw_addr(bBhi, nrow, kc));
                ldmat_x4(bl[0], bl[1], bl[2], bl[3], sw_addr(bBlo, nrow, kc));
#pragma unroll
                for (int mi = 0; mi < 2; mi++) {
                    mma_bf16(acc[mi][ng * 2],     ahi[mi], bh[0], bh[1]);
                    mma_bf16(acc[mi][ng * 2],     ahi[mi], bl[0], bl[1]);
                    mma_bf16(acc[mi][ng * 2],     alo[mi], bh[0], bh[1]);
                    mma_bf16(acc[mi][ng * 2 + 1], ahi[mi], bh[2], bh[3]);
                    mma_bf16(acc[mi][ng * 2 + 1], ahi[mi], bl[2], bl[3]);
                    mma_bf16(acc[mi][ng * 2 + 1], alo[mi], bh[2], bh[3]);
                }
            }
        }
    }

    // epilogue: c frag layout: lane -> rows (l>>2), (l>>2)+8; cols (l&3)*2, +1
#pragma unroll
    for (int mi = 0; mi < 2; mi++) {
        int r0 = bm + wm * 32 + mi * 16 + (lane >> 2);
#pragma unroll
        for (int ni = 0; ni < 8; ni++) {
            int col = wn * 64 + ni * 8 + (lane & 3) * 2;
            float* a = acc[mi][ni];
            if (MODE == 0) {
                if (r0 < NN)
                    *(float2*)&d_h0[(size_t)r0 * 256 + bn + col] = make_float2(a[0], a[1]);
                if (r0 + 8 < NN)
                    *(float2*)&d_h0[(size_t)(r0 + 8) * 256 + bn + col] = make_float2(a[2], a[3]);
            } else {
                float bx = d_bcat[bn + col], by = d_bcat[bn + col + 1];
                size_t half = (bn == 0) ? 0 : (size_t)NN * OUTC;
                if (r0 < NN)
                    *(float2*)&Cp[half + (size_t)r0 * OUTC + col] =
                        make_float2(a[0] + bx, a[1] + by);
                if (r0 + 8 < NN)
                    *(float2*)&Cp[half + (size_t)(r0 + 8) * OUTC + col] =
                        make_float2(a[2] + bx, a[3] + by);
            }
        }
    }
}

// ---------------- launch ----------------
extern "C" void kernel_launch(void* const* d_in, const int* in_sizes, int n_in,
                              void* d_out, int out_size) {
    const float* x   = (const float*)d_in[0];
    const void*  ei  = d_in[1];
    const float* W1  = (const float*)d_in[2];
    const float* b1  = (const float*)d_in[3];
    const float* Wmu = (const float*)d_in[4];
    const float* bmu = (const float*)d_in[5];
    const float* Wls = (const float*)d_in[6];
    const float* bls = (const float*)d_in[7];
    float* out = (float*)d_out;

    cudaFuncSetAttribute(k_gemm_mma<0>, cudaFuncAttributeMaxDynamicSharedMemorySize, GSMEM);
    cudaFuncSetAttribute(k_gemm_mma<1>, cudaFuncAttributeMaxDynamicSharedMemorySize, GSMEM);

    k_init<<<(NN + 255) / 256, 256>>>((const unsigned long long*)ei);
    k_pack2<<<(65536 + 255) / 256, 256>>>(W1, Wmu, Wls, bmu, bls);
    k_count<<<(EE + 255) / 256, 256>>>(ei);
    k_scan<<<1, 1024>>>();
    k_fill<<<(EE + 255) / 256, 256>>>(ei);

    dim3 ggrid(2, (NN + 127) / 128);
    k_gemm_mma<0><<<ggrid, 256, GSMEM>>>(x, nullptr);

    dim3 agrid((NN + 3) / 4);
    dim3 ablk(64, 4);
    k_agg<0><<<agrid, ablk>>>(b1);
    k_agg<1><<<agrid, ablk>>>(nullptr);

    k_gemm_mma<1><<<ggrid, 256, GSMEM>>>(nullptr, out);
}

// round 9
// speedup vs baseline: 1.5310x; 1.1456x over previous
#include <cuda_runtime.h>
#include <cuda_bf16.h>
#include <cstdint>

#define NN   50000
#define EE   800000
#define HIDC 256
#define OUTC 128
#define NB_S 98   // ceil(NN/512)

// ---------------- scratch (static device globals; no allocation) ----------------
__device__ int   d_is64;
__device__ int   d_deg[NN];
__device__ float d_dinv[NN];
__device__ int   d_rowptr[NN + 1];
__device__ int   d_cursor[NN];
__device__ int   d_bsum[NB_S];
__device__ int   d_boff[NB_S];
__device__ int2  d_csr[EE];                    // (src, w as float bits)
__device__ float d_h0[(size_t)NN * HIDC];      // x @ W1
__device__ float d_h [(size_t)NN * HIDC];      // relu(Agg(h0) + b1)
__device__ __nv_bfloat16 d_ghi[(size_t)NN * HIDC];  // split of Agg(h)
__device__ __nv_bfloat16 d_glo[(size_t)NN * HIDC];
__device__ __nv_bfloat16 d_W1Thi[HIDC * HIDC];  // W1^T  [n][k]
__device__ __nv_bfloat16 d_W1Tlo[HIDC * HIDC];
__device__ __nv_bfloat16 d_BcThi[HIDC * HIDC];  // [Wmu|Wls]^T  [n][k]
__device__ __nv_bfloat16 d_BcTlo[HIDC * HIDC];
__device__ float d_bcat[256];                   // [b_mu | b_ls]

// ---------------- helpers ----------------
__device__ __forceinline__ uint32_t smem_u32(const void* p) {
    uint32_t a;
    asm("{ .reg .u64 t; cvta.to.shared.u64 t, %1; cvt.u32.u64 %0, t; }" : "=r"(a) : "l"(p));
    return a;
}
__device__ __forceinline__ void bsplit(float v, __nv_bfloat16& h, __nv_bfloat16& l) {
    h = __float2bfloat16(v);
    l = __float2bfloat16(v - __bfloat162float(h));
}
__device__ __forceinline__ void split2(float a, float b, uint32_t& h, uint32_t& l) {
    __nv_bfloat16 ha, la, hb, lb;
    bsplit(a, ha, la);
    bsplit(b, hb, lb);
    h = (uint32_t)__bfloat16_as_ushort(ha) | ((uint32_t)__bfloat16_as_ushort(hb) << 16);
    l = (uint32_t)__bfloat16_as_ushort(la) | ((uint32_t)__bfloat16_as_ushort(lb) << 16);
}
__device__ __forceinline__ void ldmat_x4(uint32_t& r0, uint32_t& r1, uint32_t& r2,
                                         uint32_t& r3, uint32_t addr) {
    asm volatile("ldmatrix.sync.aligned.m8n8.x4.shared.b16 {%0,%1,%2,%3}, [%4];"
                 : "=r"(r0), "=r"(r1), "=r"(r2), "=r"(r3) : "r"(addr));
}
__device__ __forceinline__ void mma_bf16(float* c, const uint32_t* a,
                                         uint32_t b0, uint32_t b1) {
    asm volatile("mma.sync.aligned.m16n8k16.row.col.f32.bf16.bf16.f32 "
                 "{%0,%1,%2,%3}, {%4,%5,%6,%7}, {%8,%9}, {%0,%1,%2,%3};"
                 : "+f"(c[0]), "+f"(c[1]), "+f"(c[2]), "+f"(c[3])
                 : "r"(a[0]), "r"(a[1]), "r"(a[2]), "r"(a[3]), "r"(b0), "r"(b1));
}
__device__ __forceinline__ uint32_t sw_addr(uint32_t base, int row, int kc) {
    return base + row * 128 + ((kc ^ (row & 7)) << 4);
}
__device__ __forceinline__ int load_idx(const void* ei, size_t pos) {
    if (d_is64) return (int)((const long long*)ei)[pos];
    return ((const int*)ei)[pos];
}

// ---------------- setup kernels ----------------
// zero deg + detect edge dtype
__global__ void k_zero(const unsigned long long* __restrict__ ei) {
    int i = blockIdx.x * 256 + threadIdx.x;
    if (i < NN) d_deg[i] = 0;
    if (i == 0) {
        int is64 = 1;
        for (int j = 0; j < 128; j++)
            if (ei[j] >= (1ull << 32)) { is64 = 0; break; }
        d_is64 = is64;
    }
}
__global__ void k_count(const void* __restrict__ ei) {
    int e = blockIdx.x * 256 + threadIdx.x;
    if (e < EE) atomicAdd(&d_deg[load_idx(ei, (size_t)EE + e)], 1);
}
// ---- 3-phase parallel scan over d_deg (edge-only counts; self-loop via +1 in dinv)
__global__ __launch_bounds__(512) void k_scan1() {
    __shared__ int sw[16];
    int b = blockIdx.x, tid = threadIdx.x;
    int i = b * 512 + tid;
    int lane = tid & 31, wid = tid >> 5;
    int deg = (i < NN) ? d_deg[i] : 0;
    if (i < NN) d_dinv[i] = rsqrtf((float)(deg + 1));
    int x = deg;
#pragma unroll
    for (int d = 1; d < 32; d <<= 1) {
        int t = __shfl_up_sync(0xffffffffu, x, d);
        if (lane >= d) x += t;
    }
    if (lane == 31) sw[wid] = x;
    __syncthreads();
    if (wid == 0 && lane < 16) {
        int y = sw[lane];
#pragma unroll
        for (int d = 1; d < 16; d <<= 1) {
            int t = __shfl_up_sync(0xffffu, y, d);
            if (lane >= d) y += t;
        }
        sw[lane] = y;
    }
    __syncthreads();
    int incl = x + ((wid > 0) ? sw[wid - 1] : 0);
    if (i < NN) d_rowptr[i + 1] = incl;
    if (tid == 511) d_bsum[b] = incl;
}
__global__ __launch_bounds__(128) void k_scan2() {
    __shared__ int sw[4];
    int tid = threadIdx.x, lane = tid & 31, wid = tid >> 5;
    int v = (tid < NB_S) ? d_bsum[tid] : 0;
    int x = v;
#pragma unroll
    for (int d = 1; d < 32; d <<= 1) {
        int t = __shfl_up_sync(0xffffffffu, x, d);
        if (lane >= d) x += t;
    }
    if (lane == 31) sw[wid] = x;
    __syncthreads();
    if (wid == 0 && lane < 4) {
        int y = sw[lane];
#pragma unroll
        for (int d = 1; d < 4; d <<= 1) {
            int t = __shfl_up_sync(0xfu, y, d);
            if (lane >= d) y += t;
        }
        sw[lane] = y;
    }
    __syncthreads();
    int incl = x + ((wid > 0) ? sw[wid - 1] : 0);
    if (tid < NB_S) d_boff[tid] = incl - v;  // exclusive
}
__global__ __launch_bounds__(512) void k_scan3() {
    int i = blockIdx.x * 512 + threadIdx.x;
    if (i < NN) {
        int r = d_rowptr[i + 1] + d_boff[i >> 9];
        d_rowptr[i + 1] = r;
        d_cursor[i]     = r - d_deg[i];
    }
    if (i == 0) d_rowptr[0] = 0;
}
__global__ void k_fill(const void* __restrict__ ei) {
    int e = blockIdx.x * 256 + threadIdx.x;
    if (e < EE) {
        int s = load_idx(ei, (size_t)e);
        int d = load_idx(ei, (size_t)EE + e);
        int pos = atomicAdd(&d_cursor[d], 1);
        d_csr[pos] = make_int2(s, __float_as_int(d_dinv[s] * d_dinv[d]));
    }
}

// pack + transpose + bf16-split the weights
__global__ void k_pack2(const float* __restrict__ W1,
                        const float* __restrict__ Wmu, const float* __restrict__ Wls,
                        const float* __restrict__ bmu, const float* __restrict__ bls) {
    int idx = blockIdx.x * 256 + threadIdx.x;
    if (idx < 65536) {
        int n = idx >> 8, k = idx & 255;
        bsplit(W1[k * 256 + n], d_W1Thi[idx], d_W1Tlo[idx]);
        float bc = (n < OUTC) ? Wmu[k * OUTC + n] : Wls[k * OUTC + (n - OUTC)];
        bsplit(bc, d_BcThi[idx], d_BcTlo[idx]);
    }
    if (idx < 256) d_bcat[idx] = (idx < OUTC) ? bmu[idx] : bls[idx - OUTC];
}

// ---------------- aggregation (gather via CSR, no float atomics) ----------------
// BUF=0: d_h0 -> d_h (relu+bias). BUF=1: d_h -> (d_ghi, d_glo).
template <int BUF>
__global__ __launch_bounds__(256) void k_agg(const float* __restrict__ bias) {
    int node = blockIdx.x * 4 + threadIdx.y;
    if (node >= NN) return;
    int f4 = threadIdx.x;  // 0..63
    const float4* sf = (BUF == 0) ? (const float4*)d_h0 : (const float4*)d_h;

    float di = d_dinv[node];
    float w0 = di * di;
    float4 acc = sf[(size_t)node * 64 + f4];
    acc.x *= w0; acc.y *= w0; acc.z *= w0; acc.w *= w0;

    int beg = d_rowptr[node], end = d_rowptr[node + 1];
    int e = beg;
    for (; e + 4 <= end; e += 4) {
        int2 c0 = d_csr[e];
        int2 c1 = d_csr[e + 1];
        int2 c2 = d_csr[e + 2];
        int2 c3 = d_csr[e + 3];
        float4 v0 = sf[(size_t)c0.x * 64 + f4];
        float4 v1 = sf[(size_t)c1.x * 64 + f4];
        float4 v2 = sf[(size_t)c2.x * 64 + f4];
        float4 v3 = sf[(size_t)c3.x * 64 + f4];
        float w0f = __int_as_float(c0.y), w1f = __int_as_float(c1.y);
        float w2f = __int_as_float(c2.y), w3f = __int_as_float(c3.y);
        acc.x += w0f * v0.x + w1f * v1.x + w2f * v2.x + w3f * v3.x;
        acc.y += w0f * v0.y + w1f * v1.y + w2f * v2.y + w3f * v3.y;
        acc.z += w0f * v0.z + w1f * v1.z + w2f * v2.z + w3f * v3.z;
        acc.w += w0f * v0.w + w1f * v1.w + w2f * v2.w + w3f * v3.w;
    }
    for (; e < end; e++) {
        int2 c = d_csr[e];
        float w = __int_as_float(c.y);
        float4 v = sf[(size_t)c.x * 64 + f4];
        acc.x += w * v.x;
        acc.y += w * v.y;
        acc.z += w * v.z;
        acc.w += w * v.w;
    }
    if (BUF == 0) {
        float4 b = ((const float4*)bias)[f4];
        acc.x = fmaxf(acc.x + b.x, 0.f);
        acc.y = fmaxf(acc.y + b.y, 0.f);
        acc.z = fmaxf(acc.z + b.z, 0.f);
        acc.w = fmaxf(acc.w + b.w, 0.f);
        ((float4*)d_h)[(size_t)node * 64 + f4] = acc;
    } else {
        uint2 hv, lv;
        split2(acc.x, acc.y, hv.x, lv.x);
        split2(acc.z, acc.w, hv.y, lv.y);
        *(uint2*)&d_ghi[(size_t)node * 256 + f4 * 4] = hv;
        *(uint2*)&d_glo[(size_t)node * 256 + f4 * 4] = lv;
    }
}

// ---------------- mma.sync bf16-split GEMM ----------------
#define TILE_B 16384          // 128 rows x 128 bytes (64 bf16), swizzled
#define GSMEM  (4 * TILE_B)

__device__ __forceinline__ void load_tile64(char* tile, const __nv_bfloat16* __restrict__ src,
                                            int row0, int nvalid, int col0) {
    int t = threadIdx.x;
    int r = t >> 1;
    int hb = (t & 1) * 64;
    const char* srow = (const char*)(src + (size_t)(row0 + r) * 256 + col0);
    bool valid = r < nvalid;
#pragma unroll
    for (int i = 0; i < 4; i++) {
        int b = hb + i * 16;
        uint4 v = valid ? *(const uint4*)(srow + b) : make_uint4(0u, 0u, 0u, 0u);
        uint32_t off = (uint32_t)(r * 128 + b);
        off ^= ((off >> 3) & 0x70);
        *(uint4*)(tile + off) = v;
    }
}

__device__ __forceinline__ void load_tile64_split(char* tilehi, char* tilelo,
                                                  const float* __restrict__ src,
                                                  int row0, int nvalid, int col0) {
    int t = threadIdx.x;
    int r = t >> 1;
    int hf = (t & 1) * 32;
    const float* srow = src + (size_t)(row0 + r) * 256 + col0 + hf;
    bool valid = r < nvalid;
#pragma unroll
    for (int i = 0; i < 4; i++) {
        float4 f0 = valid ? *(const float4*)(srow + i * 8)     : make_float4(0.f, 0.f, 0.f, 0.f);
        float4 f1 = valid ? *(const float4*)(srow + i * 8 + 4) : make_float4(0.f, 0.f, 0.f, 0.f);
        uint4 hv, lv;
        split2(f0.x, f0.y, hv.x, lv.x);
        split2(f0.z, f0.w, hv.y, lv.y);
        split2(f1.x, f1.y, hv.z, lv.z);
        split2(f1.z, f1.w, hv.w, lv.w);
        uint32_t off = (uint32_t)(r * 128 + hf * 2 + i * 16);
        off ^= ((off >> 3) & 0x70);
        *(uint4*)(tilehi + off) = hv;
        *(uint4*)(tilelo + off) = lv;
    }
}

template <int MODE>
__global__ __launch_bounds__(256) void k_gemm_mma(const float* __restrict__ Ax,
                                                  float* __restrict__ Cp) {
    extern __shared__ char smem[];
    char* sAhi = smem;
    char* sAlo = smem + TILE_B;
    char* sBhi = smem + 2 * TILE_B;
    char* sBlo = smem + 3 * TILE_B;
    uint32_t bAhi = smem_u32(sAhi), bAlo = bAhi + TILE_B;
    uint32_t bBhi = bAhi + 2 * TILE_B, bBlo = bAhi + 3 * TILE_B;

    int tid = threadIdx.x, wid = tid >> 5, lane = tid & 31;
    int wm = wid >> 1, wn = wid & 1;
    int bn = blockIdx.x * 128;
    int bm = blockIdx.y * 128;

    const __nv_bfloat16* Bhi = (MODE == 0) ? d_W1Thi : d_BcThi;
    const __nv_bfloat16* Blo = (MODE == 0) ? d_W1Tlo : d_BcTlo;

    int navalid = NN - bm; if (navalid > 128) navalid = 128;

    float acc[2][8][4];
#pragma unroll
    for (int i = 0; i < 2; i++)
#pragma unroll
        for (int j = 0; j < 8; j++)
#pragma unroll
            for (int q = 0; q < 4; q++) acc[i][j][q] = 0.f;

    int a_row_off = ((lane >> 3) & 1) * 8 + (lane & 7);
    int a_kc_off  = (lane >> 4);
    int b_row_off = (lane >> 4) * 8 + (lane & 7);
    int b_kc_off  = ((lane >> 3) & 1);

    for (int c = 0; c < 4; c++) {
        if (c > 0) __syncthreads();
        if (MODE == 0) {
            load_tile64_split(sAhi, sAlo, Ax, bm, navalid, c * 64);
        } else {
            load_tile64(sAhi, d_ghi, bm, navalid, c * 64);
            load_tile64(sAlo, d_glo, bm, navalid, c * 64);
        }
        load_tile64(sBhi, Bhi, bn, 128, c * 64);
        load_tile64(sBlo, Blo, bn, 128, c * 64);
        __syncthreads();

#pragma unroll
        for (int ks = 0; ks < 4; ks++) {
            int kc0 = ks * 2;
            uint32_t ahi[2][4], alo[2][4];
#pragma unroll
            for (int mi = 0; mi < 2; mi++) {
                int row = wm * 32 + mi * 16 + a_row_off;
                int kc  = kc0 + a_kc_off;
                ldmat_x4(ahi[mi][0], ahi[mi][1], ahi[mi][2], ahi[mi][3],
                         sw_addr(bAhi, row, kc));
                ldmat_x4(alo[mi][0], alo[mi][1], alo[mi][2], alo[mi][3],
                         sw_addr(bAlo, row, kc));
            }
#pragma unroll
            for (int ng = 0; ng < 4; ng++) {
                int nrow = wn * 64 + ng * 16 + b_row_off;
                int kc   = kc0 + b_kc_off;
                uint32_t bh[4], bl[4];
                ldmat_x4(bh[0], bh[1], bh[2], bh[3], sw_addr(bBhi, nrow, kc));
                ldmat_x4(bl[0], bl[1], bl[2], bl[3], sw_addr(bBlo, nrow, kc));
#pragma unroll
                for (int mi = 0; mi < 2; mi++) {
                    mma_bf16(acc[mi][ng * 2],     ahi[mi], bh[0], bh[1]);
                    mma_bf16(acc[mi][ng * 2],     ahi[mi], bl[0], bl[1]);
                    mma_bf16(acc[mi][ng * 2],     alo[mi], bh[0], bh[1]);
                    mma_bf16(acc[mi][ng * 2 + 1], ahi[mi], bh[2], bh[3]);
                    mma_bf16(acc[mi][ng * 2 + 1], ahi[mi], bl[2], bl[3]);
                    mma_bf16(acc[mi][ng * 2 + 1], alo[mi], bh[2], bh[3]);
                }
            }
        }
    }

#pragma unroll
    for (int mi = 0; mi < 2; mi++) {
        int r0 = bm + wm * 32 + mi * 16 + (lane >> 2);
#pragma unroll
        for (int ni = 0; ni < 8; ni++) {
            int col = wn * 64 + ni * 8 + (lane & 3) * 2;
            float* a = acc[mi][ni];
            if (MODE == 0) {
                if (r0 < NN)
                    *(float2*)&d_h0[(size_t)r0 * 256 + bn + col] = make_float2(a[0], a[1]);
                if (r0 + 8 < NN)
                    *(float2*)&d_h0[(size_t)(r0 + 8) * 256 + bn + col] = make_float2(a[2], a[3]);
            } else {
                float bx = d_bcat[bn + col], by = d_bcat[bn + col + 1];
                size_t half = (bn == 0) ? 0 : (size_t)NN * OUTC;
                if (r0 < NN)
                    *(float2*)&Cp[half + (size_t)r0 * OUTC + col] =
                        make_float2(a[0] + bx, a[1] + by);
                if (r0 + 8 < NN)
                    *(float2*)&Cp[half + (size_t)(r0 + 8) * OUTC + col] =
                        make_float2(a[2] + bx, a[3] + by);
            }
        }
    }
}

// ---------------- launch ----------------
extern "C" void kernel_launch(void* const* d_in, const int* in_sizes, int n_in,
                              void* d_out, int out_size) {
    const float* x   = (const float*)d_in[0];
    const void*  ei  = d_in[1];
    const float* W1  = (const float*)d_in[2];
    const float* b1  = (const float*)d_in[3];
    const float* Wmu = (const float*)d_in[4];
    const float* bmu = (const float*)d_in[5];
    const float* Wls = (const float*)d_in[6];
    const float* bls = (const float*)d_in[7];
    float* out = (float*)d_out;

    cudaFuncSetAttribute(k_gemm_mma<0>, cudaFuncAttributeMaxDynamicSharedMemorySize, GSMEM);
    cudaFuncSetAttribute(k_gemm_mma<1>, cudaFuncAttributeMaxDynamicSharedMemorySize, GSMEM);

    dim3 ggrid(2, (NN + 127) / 128);
    dim3 agrid((NN + 3) / 4);
    dim3 ablk(64, 4);

    // fork a side stream for the weight-pack + GEMM0 branch (independent of CSR build)
    cudaStream_t s1;
    cudaStreamCreateWithFlags(&s1, cudaStreamNonBlocking);
    cudaEvent_t e0, e1;
    cudaEventCreateWithFlags(&e0, cudaEventDisableTiming);
    cudaEventCreateWithFlags(&e1, cudaEventDisableTiming);

    cudaEventRecord(e0, 0);
    cudaStreamWaitEvent(s1, e0, 0);

    // branch B (s1): pack weights, then GEMM0 (x @ W1 -> d_h0)
    k_pack2<<<(65536 + 255) / 256, 256, 0, s1>>>(W1, Wmu, Wls, bmu, bls);
    k_gemm_mma<0><<<ggrid, 256, GSMEM, s1>>>(x, nullptr);
    cudaEventRecord(e1, s1);

    // branch A (default stream): CSR build
    k_zero<<<(NN + 255) / 256, 256>>>((const unsigned long long*)ei);
    k_count<<<(EE + 255) / 256, 256>>>(ei);
    k_scan1<<<NB_S, 512>>>();
    k_scan2<<<1, 128>>>();
    k_scan3<<<NB_S, 512>>>();
    k_fill<<<(EE + 255) / 256, 256>>>(ei);

    // join: aggregation needs d_h0 (branch B) and CSR (branch A)
    cudaStreamWaitEvent(0, e1, 0);
    k_agg<0><<<agrid, ablk>>>(b1);
    k_agg<1><<<agrid, ablk>>>(nullptr);
    k_gemm_mma<1><<<ggrid, 256, GSMEM>>>(nullptr, out);
}